// round 2
// baseline (speedup 1.0000x reference)
#include <cuda_runtime.h>

#define BATCH  4096
#define TSTEPS 100
#define DDIM   100
#define OOUT   3
#define NROWS  (BATCH * TSTEPS)        // 409600 independent dot products
#define CWIDTH (BATCH * OOUT)          // 12288

// Scratch: cur[t][b*3+c] = spikes(b,t,:) . W[c,:] + bias[c]   (4.9 MB)
__device__ float g_cur[TSTEPS * CWIDTH];

// ---------------- Kernel 1: all (b,t) dot products, massively parallel ------
__global__ __launch_bounds__(256) void cur_kernel(
    const float* __restrict__ x, const float* __restrict__ u,
    const float* __restrict__ W, const float* __restrict__ bias)
{
    const int gw   = (blockIdx.x * blockDim.x + threadIdx.x) >> 5;  // row id
    const int lane = threadIdx.x & 31;
    if (gw >= NROWS) return;

    const int b = gw / TSTEPS;
    const int t = gw - b * TSTEPS;

    const bool act = (lane < (DDIM / 4));   // 25 active lanes
    float4 w0 = make_float4(0.f,0.f,0.f,0.f), w1 = w0, w2 = w0;
    float4 xv = w0, uv = w0;
    if (act) {
        w0 = *(const float4*)(W + 0 * DDIM + 4 * lane);
        w1 = *(const float4*)(W + 1 * DDIM + 4 * lane);
        w2 = *(const float4*)(W + 2 * DDIM + 4 * lane);
        const size_t off = (size_t)b * (TSTEPS * DDIM) + (size_t)t * DDIM;
        xv = __ldg((const float4*)(x + off) + lane);
        uv = __ldg((const float4*)(u + off) + lane);
    }

    float p0 = 0.f, p1 = 0.f, p2 = 0.f;
    if (act) {
        if (uv.x < xv.x) { p0 += w0.x; p1 += w1.x; p2 += w2.x; }
        if (uv.y < xv.y) { p0 += w0.y; p1 += w1.y; p2 += w2.y; }
        if (uv.z < xv.z) { p0 += w0.z; p1 += w1.z; p2 += w2.z; }
        if (uv.w < xv.w) { p0 += w0.w; p1 += w1.w; p2 += w2.w; }
    }
    #pragma unroll
    for (int off = 16; off; off >>= 1) {
        p0 += __shfl_xor_sync(0xffffffffu, p0, off);
        p1 += __shfl_xor_sync(0xffffffffu, p1, off);
        p2 += __shfl_xor_sync(0xffffffffu, p2, off);
    }

    if (lane == 0) {
        float* dst = g_cur + (size_t)t * CWIDTH + (size_t)b * OOUT;
        dst[0] = p0 + __ldg(bias + 0);
        dst[1] = p1 + __ldg(bias + 1);
        dst[2] = p2 + __ldg(bias + 2);
    }
}

// ---------------- Kernel 2: tiny serial leaky scan, thread per (b, c) -------
__global__ __launch_bounds__(256) void scan_kernel(
    const float* __restrict__ betap, const float* __restrict__ thrp,
    float* __restrict__ out)
{
    const int tid = blockIdx.x * blockDim.x + threadIdx.x;  // < 12288
    if (tid >= CWIDTH) return;

    const float beta = __ldg(betap);
    const float thr  = __ldg(thrp);

    float* __restrict__ spk = out;
    float* __restrict__ mem = out + (size_t)TSTEPS * CWIDTH;

    float m = 0.f;
    #pragma unroll
    for (int t = 0; t < TSTEPS; ++t) {
        const float cu = g_cur[(size_t)t * CWIDTH + tid];   // independent loads: prefetchable
        const float r  = (m - thr > 0.f) ? thr : 0.f;       // reset from PREVIOUS mem
        m = beta * m + cu - r;
        spk[(size_t)t * CWIDTH + tid] = (m - thr > 0.f) ? 1.f : 0.f;
        mem[(size_t)t * CWIDTH + tid] = m;
    }
}

extern "C" void kernel_launch(void* const* d_in, const int* in_sizes, int n_in,
                              void* d_out, int out_size)
{
    const float* x    = (const float*)d_in[0];
    const float* u    = (const float*)d_in[1];
    const float* W    = (const float*)d_in[2];
    const float* bias = (const float*)d_in[3];
    const float* beta = (const float*)d_in[4];
    const float* thr  = (const float*)d_in[5];
    float* out = (float*)d_out;

    // K1: one warp per (b,t) row -> 409600 warps -> 51200 blocks of 256
    const int blocks1 = (NROWS * 32) / 256;
    cur_kernel<<<blocks1, 256>>>(x, u, W, bias);

    // K2: one thread per (b, c) -> 12288 threads
    const int blocks2 = (CWIDTH + 255) / 256;
    scan_kernel<<<blocks2, 256>>>(beta, thr, out);
}

// round 3
// speedup vs baseline: 1.6421x; 1.6421x over previous
#include <cuda_runtime.h>

#define BATCH  4096
#define TSTEPS 100
#define DDIM   100
#define OOUT   3
#define CW     (BATCH * OOUT)

// One warp per batch element; 2 timesteps per loop iteration.
// Lanes 0..24 hold float4 chunks of the 100-float rows; interleaved butterfly
// reduction for the two rows; lanes 0..2 store their own output channel.
__global__ __launch_bounds__(128, 7) void leaky_fused(
    const float* __restrict__ x, const float* __restrict__ u,
    const float* __restrict__ W, const float* __restrict__ bias,
    const float* __restrict__ betap, const float* __restrict__ thrp,
    float* __restrict__ out)
{
    const int gw   = (blockIdx.x << 2) | (threadIdx.x >> 5);  // batch id (grid exact)
    const int lane = threadIdx.x & 31;

    const float beta = __ldg(betap);
    const float thr  = __ldg(thrp);
    const float b0 = __ldg(bias + 0);
    const float b1 = __ldg(bias + 1);
    const float b2 = __ldg(bias + 2);

    const bool act = (lane < (DDIM / 4));   // 25 active lanes
    const float4 z = make_float4(0.f, 0.f, 0.f, 0.f);
    float4 w0 = z, w1 = z, w2 = z;
    if (act) {
        w0 = *(const float4*)(W + 0 * DDIM + 4 * lane);
        w1 = *(const float4*)(W + 1 * DDIM + 4 * lane);
        w2 = *(const float4*)(W + 2 * DDIM + 4 * lane);
    }

    const float4* __restrict__ xr = (const float4*)(x + (size_t)gw * (TSTEPS * DDIM));
    const float4* __restrict__ ur = (const float4*)(u + (size_t)gw * (TSTEPS * DDIM));

    float* __restrict__ spk = out;
    float* __restrict__ mem = out + (size_t)TSTEPS * CW;

    // current pair of rows (t, t+1)
    float4 xa = z, ua = z, xb = z, ub = z;
    if (act) {
        xa = __ldg(xr + lane);                ua = __ldg(ur + lane);
        xb = __ldg(xr + (DDIM / 4) + lane);   ub = __ldg(ur + (DDIM / 4) + lane);
    }

    float m0 = 0.f, m1 = 0.f, m2 = 0.f;

    for (int t = 0; t < TSTEPS; t += 2) {
        // prefetch next pair (4 loads in flight during compute)
        float4 xa2 = z, ua2 = z, xb2 = z, ub2 = z;
        if (act && (t + 2 < TSTEPS)) {
            const int base = (t + 2) * (DDIM / 4) + lane;
            xa2 = __ldg(xr + base);              ua2 = __ldg(ur + base);
            xb2 = __ldg(xr + base + (DDIM / 4)); ub2 = __ldg(ur + base + (DDIM / 4));
        }

        float pa0 = 0.f, pa1 = 0.f, pa2 = 0.f;
        float pb0 = 0.f, pb1 = 0.f, pb2 = 0.f;
        if (act) {
            if (ua.x < xa.x) { pa0 += w0.x; pa1 += w1.x; pa2 += w2.x; }
            if (ua.y < xa.y) { pa0 += w0.y; pa1 += w1.y; pa2 += w2.y; }
            if (ua.z < xa.z) { pa0 += w0.z; pa1 += w1.z; pa2 += w2.z; }
            if (ua.w < xa.w) { pa0 += w0.w; pa1 += w1.w; pa2 += w2.w; }
            if (ub.x < xb.x) { pb0 += w0.x; pb1 += w1.x; pb2 += w2.x; }
            if (ub.y < xb.y) { pb0 += w0.y; pb1 += w1.y; pb2 += w2.y; }
            if (ub.z < xb.z) { pb0 += w0.z; pb1 += w1.z; pb2 += w2.z; }
            if (ub.w < xb.w) { pb0 += w0.w; pb1 += w1.w; pb2 += w2.w; }
        }

        // interleaved butterflies: two independent 5-level chains
        #pragma unroll
        for (int o = 16; o; o >>= 1) {
            pa0 += __shfl_xor_sync(0xffffffffu, pa0, o);
            pb0 += __shfl_xor_sync(0xffffffffu, pb0, o);
            pa1 += __shfl_xor_sync(0xffffffffu, pa1, o);
            pb1 += __shfl_xor_sync(0xffffffffu, pb1, o);
            pa2 += __shfl_xor_sync(0xffffffffu, pa2, o);
            pb2 += __shfl_xor_sync(0xffffffffu, pb2, o);
        }

        // ---- step t (row A) ----
        {
            const float r0 = (m0 - thr > 0.f) ? thr : 0.f;
            const float r1 = (m1 - thr > 0.f) ? thr : 0.f;
            const float r2 = (m2 - thr > 0.f) ? thr : 0.f;
            m0 = beta * m0 + (pa0 + b0) - r0;
            m1 = beta * m1 + (pa1 + b1) - r1;
            m2 = beta * m2 + (pa2 + b2) - r2;
            if (lane < OOUT) {
                const float mm = (lane == 0) ? m0 : ((lane == 1) ? m1 : m2);
                const size_t o1 = (size_t)t * CW + (size_t)gw * OOUT + lane;
                spk[o1] = (mm - thr > 0.f) ? 1.f : 0.f;
                mem[o1] = mm;
            }
        }
        // ---- step t+1 (row B) ----
        {
            const float r0 = (m0 - thr > 0.f) ? thr : 0.f;
            const float r1 = (m1 - thr > 0.f) ? thr : 0.f;
            const float r2 = (m2 - thr > 0.f) ? thr : 0.f;
            m0 = beta * m0 + (pb0 + b0) - r0;
            m1 = beta * m1 + (pb1 + b1) - r1;
            m2 = beta * m2 + (pb2 + b2) - r2;
            if (lane < OOUT) {
                const float mm = (lane == 0) ? m0 : ((lane == 1) ? m1 : m2);
                const size_t o2 = (size_t)(t + 1) * CW + (size_t)gw * OOUT + lane;
                spk[o2] = (mm - thr > 0.f) ? 1.f : 0.f;
                mem[o2] = mm;
            }
        }

        xa = xa2; ua = ua2; xb = xb2; ub = ub2;
    }
}

extern "C" void kernel_launch(void* const* d_in, const int* in_sizes, int n_in,
                              void* d_out, int out_size)
{
    const float* x    = (const float*)d_in[0];
    const float* u    = (const float*)d_in[1];
    const float* W    = (const float*)d_in[2];
    const float* bias = (const float*)d_in[3];
    const float* beta = (const float*)d_in[4];
    const float* thr  = (const float*)d_in[5];
    float* out = (float*)d_out;

    // 4096 warps = 1024 blocks of 128 threads; single wave at 7 blocks/SM.
    leaky_fused<<<BATCH / 4, 128>>>(x, u, W, bias, beta, thr, out);
}

// round 4
// speedup vs baseline: 2.0246x; 1.2329x over previous
#include <cuda_runtime.h>

#define BATCH  4096
#define TSTEPS 100
#define DDIM   100
#define OOUT   3
#define CW     (BATCH * OOUT)

#define FPSCALE 67108864.0f          /* 2^26 */
#define INV_FPSCALE 1.490116119384765625e-8f /* 2^-26 */

// One warp per batch element; 2 timesteps per loop iteration.
// Weights held as fixed-point ints; spike-dot accumulated in int and reduced
// with a single REDUX.SUM per channel (replaces 5-level SHFL butterfly).
__global__ __launch_bounds__(128, 8) void leaky_fused(
    const float* __restrict__ x, const float* __restrict__ u,
    const float* __restrict__ W, const float* __restrict__ bias,
    const float* __restrict__ betap, const float* __restrict__ thrp,
    float* __restrict__ out)
{
    const int gw   = (blockIdx.x << 2) | (threadIdx.x >> 5);  // batch id
    const int lane = threadIdx.x & 31;

    const float beta = __ldg(betap);
    const float thr  = __ldg(thrp);
    const float b0 = __ldg(bias + 0);
    const float b1 = __ldg(bias + 1);
    const float b2 = __ldg(bias + 2);

    const bool act = (lane < (DDIM / 4));   // 25 active lanes
    const float4 z = make_float4(0.f, 0.f, 0.f, 0.f);

    // Fixed-point weights (zero on inactive lanes)
    int w0x=0,w0y=0,w0z=0,w0w=0, w1x=0,w1y=0,w1z=0,w1w=0, w2x=0,w2y=0,w2z=0,w2w=0;
    if (act) {
        float4 a = *(const float4*)(W + 0 * DDIM + 4 * lane);
        float4 b = *(const float4*)(W + 1 * DDIM + 4 * lane);
        float4 c = *(const float4*)(W + 2 * DDIM + 4 * lane);
        w0x = __float2int_rn(a.x * FPSCALE); w0y = __float2int_rn(a.y * FPSCALE);
        w0z = __float2int_rn(a.z * FPSCALE); w0w = __float2int_rn(a.w * FPSCALE);
        w1x = __float2int_rn(b.x * FPSCALE); w1y = __float2int_rn(b.y * FPSCALE);
        w1z = __float2int_rn(b.z * FPSCALE); w1w = __float2int_rn(b.w * FPSCALE);
        w2x = __float2int_rn(c.x * FPSCALE); w2y = __float2int_rn(c.y * FPSCALE);
        w2z = __float2int_rn(c.z * FPSCALE); w2w = __float2int_rn(c.w * FPSCALE);
    }

    const float4* __restrict__ xr = (const float4*)(x + (size_t)gw * (TSTEPS * DDIM));
    const float4* __restrict__ ur = (const float4*)(u + (size_t)gw * (TSTEPS * DDIM));

    float* __restrict__ spk = out;
    float* __restrict__ mem = out + (size_t)TSTEPS * CW;

    // current pair of rows (t, t+1); streaming loads (no reuse)
    float4 xa = z, ua = z, xb = z, ub = z;
    if (act) {
        xa = __ldcs(xr + lane);                ua = __ldcs(ur + lane);
        xb = __ldcs(xr + (DDIM / 4) + lane);   ub = __ldcs(ur + (DDIM / 4) + lane);
    }

    float m0 = 0.f, m1 = 0.f, m2 = 0.f;

    for (int t = 0; t < TSTEPS; t += 2) {
        // prefetch next pair
        float4 xa2 = z, ua2 = z, xb2 = z, ub2 = z;
        if (act && (t + 2 < TSTEPS)) {
            const int base = (t + 2) * (DDIM / 4) + lane;
            xa2 = __ldcs(xr + base);              ua2 = __ldcs(ur + base);
            xb2 = __ldcs(xr + base + (DDIM / 4)); ub2 = __ldcs(ur + base + (DDIM / 4));
        }

        int ia0 = 0, ia1 = 0, ia2 = 0, ib0 = 0, ib1 = 0, ib2 = 0;
        if (ua.x < xa.x) { ia0 += w0x; ia1 += w1x; ia2 += w2x; }
        if (ua.y < xa.y) { ia0 += w0y; ia1 += w1y; ia2 += w2y; }
        if (ua.z < xa.z) { ia0 += w0z; ia1 += w1z; ia2 += w2z; }
        if (ua.w < xa.w) { ia0 += w0w; ia1 += w1w; ia2 += w2w; }
        if (ub.x < xb.x) { ib0 += w0x; ib1 += w1x; ib2 += w2x; }
        if (ub.y < xb.y) { ib0 += w0y; ib1 += w1y; ib2 += w2y; }
        if (ub.z < xb.z) { ib0 += w0z; ib1 += w1z; ib2 += w2z; }
        if (ub.w < xb.w) { ib0 += w0w; ib1 += w1w; ib2 += w2w; }

        // single-instruction warp reductions (all lanes receive the sum)
        const float pa0 = (float)__reduce_add_sync(0xffffffffu, ia0) * INV_FPSCALE;
        const float pb0 = (float)__reduce_add_sync(0xffffffffu, ib0) * INV_FPSCALE;
        const float pa1 = (float)__reduce_add_sync(0xffffffffu, ia1) * INV_FPSCALE;
        const float pb1 = (float)__reduce_add_sync(0xffffffffu, ib1) * INV_FPSCALE;
        const float pa2 = (float)__reduce_add_sync(0xffffffffu, ia2) * INV_FPSCALE;
        const float pb2 = (float)__reduce_add_sync(0xffffffffu, ib2) * INV_FPSCALE;

        // ---- step t ----
        {
            const float r0 = (m0 - thr > 0.f) ? thr : 0.f;
            const float r1 = (m1 - thr > 0.f) ? thr : 0.f;
            const float r2 = (m2 - thr > 0.f) ? thr : 0.f;
            m0 = beta * m0 + (pa0 + b0) - r0;
            m1 = beta * m1 + (pa1 + b1) - r1;
            m2 = beta * m2 + (pa2 + b2) - r2;
            if (lane < OOUT) {
                const float mm = (lane == 0) ? m0 : ((lane == 1) ? m1 : m2);
                const size_t o1 = (size_t)t * CW + (size_t)gw * OOUT + lane;
                __stcs(spk + o1, (mm - thr > 0.f) ? 1.f : 0.f);
                __stcs(mem + o1, mm);
            }
        }
        // ---- step t+1 ----
        {
            const float r0 = (m0 - thr > 0.f) ? thr : 0.f;
            const float r1 = (m1 - thr > 0.f) ? thr : 0.f;
            const float r2 = (m2 - thr > 0.f) ? thr : 0.f;
            m0 = beta * m0 + (pb0 + b0) - r0;
            m1 = beta * m1 + (pb1 + b1) - r1;
            m2 = beta * m2 + (pb2 + b2) - r2;
            if (lane < OOUT) {
                const float mm = (lane == 0) ? m0 : ((lane == 1) ? m1 : m2);
                const size_t o2 = (size_t)(t + 1) * CW + (size_t)gw * OOUT + lane;
                __stcs(spk + o2, (mm - thr > 0.f) ? 1.f : 0.f);
                __stcs(mem + o2, mm);
            }
        }

        xa = xa2; ua = ua2; xb = xb2; ub = ub2;
    }
}

extern "C" void kernel_launch(void* const* d_in, const int* in_sizes, int n_in,
                              void* d_out, int out_size)
{
    const float* x    = (const float*)d_in[0];
    const float* u    = (const float*)d_in[1];
    const float* W    = (const float*)d_in[2];
    const float* bias = (const float*)d_in[3];
    const float* beta = (const float*)d_in[4];
    const float* thr  = (const float*)d_in[5];
    float* out = (float*)d_out;

    leaky_fused<<<BATCH / 4, 128>>>(x, u, W, bias, beta, thr, out);
}

// round 5
// speedup vs baseline: 2.0354x; 1.0054x over previous
#include <cuda_runtime.h>

#define BATCH  4096
#define TSTEPS 100
#define DDIM   100
#define OOUT   3
#define CW     (BATCH * OOUT)

#define FPSCALE 67108864.0f                       /* 2^26 */
#define INV_FPSCALE 1.490116119384765625e-8f      /* 2^-26 */

// One warp per batch element, 4 timesteps per loop iteration (2 pipelined
// row-pairs). Per lane: 4-bit spike mask -> LDS.128 LUT lookup of fixed-point
// subset sums -> REDUX.SUM per channel. Lane i (<3) owns output channel i.
__global__ __launch_bounds__(128, 8) void leaky_fused(
    const float* __restrict__ x, const float* __restrict__ u,
    const float* __restrict__ W, const float* __restrict__ bias,
    const float* __restrict__ betap, const float* __restrict__ thrp,
    float* __restrict__ out)
{
    // LUT[mask][lane] = (sum w0, sum w1, sum w2, 0) over set bits, fixed-point
    __shared__ int4 lut[16 * 32];
    for (int e = threadIdx.x; e < 16 * 32; e += 128) {
        const int mask = e >> 5;
        const int ln   = e & 31;
        int s0 = 0, s1 = 0, s2 = 0;
        if (ln < (DDIM / 4)) {
            #pragma unroll
            for (int bit = 0; bit < 4; ++bit) {
                if ((mask >> bit) & 1) {
                    const int col = ln * 4 + bit;
                    s0 += __float2int_rn(__ldg(W + 0 * DDIM + col) * FPSCALE);
                    s1 += __float2int_rn(__ldg(W + 1 * DDIM + col) * FPSCALE);
                    s2 += __float2int_rn(__ldg(W + 2 * DDIM + col) * FPSCALE);
                }
            }
        }
        lut[(mask << 5) | ln] = make_int4(s0, s1, s2, 0);
    }
    __syncthreads();

    const int gw   = (blockIdx.x << 2) | (threadIdx.x >> 5);  // batch id
    const int lane = threadIdx.x & 31;

    const float beta = __ldg(betap);
    const float thr  = __ldg(thrp);
    const float bl   = __ldg(bias + ((lane < 2) ? lane : 2)); // lane's channel bias

    const bool act = (lane < (DDIM / 4));   // 25 active load lanes
    const float4 z = make_float4(0.f, 0.f, 0.f, 0.f);

    const float4* __restrict__ xr = (const float4*)(x + (size_t)gw * (TSTEPS * DDIM));
    const float4* __restrict__ ur = (const float4*)(u + (size_t)gw * (TSTEPS * DDIM));

    float* __restrict__ spk = out;
    float* __restrict__ mem = out + (size_t)TSTEPS * CW;

    // two row-pairs in flight: P = rows (t, t+1), Q = rows (t+2, t+3)
    float4 xp0 = z, up0 = z, xp1 = z, up1 = z;
    float4 xq0 = z, uq0 = z, xq1 = z, uq1 = z;
    if (act) {
        xp0 = __ldcs(xr + 0 * (DDIM / 4) + lane);  up0 = __ldcs(ur + 0 * (DDIM / 4) + lane);
        xp1 = __ldcs(xr + 1 * (DDIM / 4) + lane);  up1 = __ldcs(ur + 1 * (DDIM / 4) + lane);
        xq0 = __ldcs(xr + 2 * (DDIM / 4) + lane);  uq0 = __ldcs(ur + 2 * (DDIM / 4) + lane);
        xq1 = __ldcs(xr + 3 * (DDIM / 4) + lane);  uq1 = __ldcs(ur + 3 * (DDIM / 4) + lane);
    }

    float m = 0.f;     // this lane's channel membrane
    float r = 0.f;     // reset = prev spike * thr

    for (int t = 0; t < TSTEPS; t += 4) {
        // ---------------- stage 1: rows t, t+1 (pair P) ----------------
        {
            const int ma = (up0.x < xp0.x) | ((up0.y < xp0.y) << 1)
                         | ((up0.z < xp0.z) << 2) | ((up0.w < xp0.w) << 3);
            const int mb = (up1.x < xp1.x) | ((up1.y < xp1.y) << 1)
                         | ((up1.z < xp1.z) << 2) | ((up1.w < xp1.w) << 3);

            // refill P with rows t+4, t+5 (in flight across stage 2)
            if (act && (t + 4 < TSTEPS)) {
                const int base = (t + 4) * (DDIM / 4) + lane;
                xp0 = __ldcs(xr + base);              up0 = __ldcs(ur + base);
                xp1 = __ldcs(xr + base + (DDIM / 4)); up1 = __ldcs(ur + base + (DDIM / 4));
            }

            const int4 la = lut[(ma << 5) | lane];
            const int4 lb = lut[(mb << 5) | lane];

            const int sa0 = __reduce_add_sync(0xffffffffu, la.x);
            const int sb0 = __reduce_add_sync(0xffffffffu, lb.x);
            const int sa1 = __reduce_add_sync(0xffffffffu, la.y);
            const int sb1 = __reduce_add_sync(0xffffffffu, lb.y);
            const int sa2 = __reduce_add_sync(0xffffffffu, la.z);
            const int sb2 = __reduce_add_sync(0xffffffffu, lb.z);

            const int ia = (lane == 0) ? sa0 : ((lane == 1) ? sa1 : sa2);
            const int ib = (lane == 0) ? sb0 : ((lane == 1) ? sb1 : sb2);
            const float pa = (float)ia * INV_FPSCALE;
            const float pb = (float)ib * INV_FPSCALE;

            // step t
            m = beta * m + (pa + bl) - r;
            float sp = (m - thr > 0.f) ? 1.f : 0.f;
            r = sp * thr;
            if (lane < OOUT) {
                const size_t o = (size_t)t * CW + (size_t)gw * OOUT + lane;
                __stcs(spk + o, sp);
                __stcs(mem + o, m);
            }
            // step t+1
            m = beta * m + (pb + bl) - r;
            sp = (m - thr > 0.f) ? 1.f : 0.f;
            r = sp * thr;
            if (lane < OOUT) {
                const size_t o = (size_t)(t + 1) * CW + (size_t)gw * OOUT + lane;
                __stcs(spk + o, sp);
                __stcs(mem + o, m);
            }
        }
        // ---------------- stage 2: rows t+2, t+3 (pair Q) ----------------
        {
            const int ma = (uq0.x < xq0.x) | ((uq0.y < xq0.y) << 1)
                         | ((uq0.z < xq0.z) << 2) | ((uq0.w < xq0.w) << 3);
            const int mb = (uq1.x < xq1.x) | ((uq1.y < xq1.y) << 1)
                         | ((uq1.z < xq1.z) << 2) | ((uq1.w < xq1.w) << 3);

            // refill Q with rows t+6, t+7
            if (act && (t + 6 < TSTEPS)) {
                const int base = (t + 6) * (DDIM / 4) + lane;
                xq0 = __ldcs(xr + base);              uq0 = __ldcs(ur + base);
                xq1 = __ldcs(xr + base + (DDIM / 4)); uq1 = __ldcs(ur + base + (DDIM / 4));
            }

            const int4 la = lut[(ma << 5) | lane];
            const int4 lb = lut[(mb << 5) | lane];

            const int sa0 = __reduce_add_sync(0xffffffffu, la.x);
            const int sb0 = __reduce_add_sync(0xffffffffu, lb.x);
            const int sa1 = __reduce_add_sync(0xffffffffu, la.y);
            const int sb1 = __reduce_add_sync(0xffffffffu, lb.y);
            const int sa2 = __reduce_add_sync(0xffffffffu, la.z);
            const int sb2 = __reduce_add_sync(0xffffffffu, lb.z);

            const int ia = (lane == 0) ? sa0 : ((lane == 1) ? sa1 : sa2);
            const int ib = (lane == 0) ? sb0 : ((lane == 1) ? sb1 : sb2);
            const float pa = (float)ia * INV_FPSCALE;
            const float pb = (float)ib * INV_FPSCALE;

            // step t+2
            m = beta * m + (pa + bl) - r;
            float sp = (m - thr > 0.f) ? 1.f : 0.f;
            r = sp * thr;
            if (lane < OOUT) {
                const size_t o = (size_t)(t + 2) * CW + (size_t)gw * OOUT + lane;
                __stcs(spk + o, sp);
                __stcs(mem + o, m);
            }
            // step t+3
            m = beta * m + (pb + bl) - r;
            sp = (m - thr > 0.f) ? 1.f : 0.f;
            r = sp * thr;
            if (lane < OOUT) {
                const size_t o = (size_t)(t + 3) * CW + (size_t)gw * OOUT + lane;
                __stcs(spk + o, sp);
                __stcs(mem + o, m);
            }
        }
    }
}

extern "C" void kernel_launch(void* const* d_in, const int* in_sizes, int n_in,
                              void* d_out, int out_size)
{
    const float* x    = (const float*)d_in[0];
    const float* u    = (const float*)d_in[1];
    const float* W    = (const float*)d_in[2];
    const float* bias = (const float*)d_in[3];
    const float* beta = (const float*)d_in[4];
    const float* thr  = (const float*)d_in[5];
    float* out = (float*)d_out;

    leaky_fused<<<BATCH / 4, 128>>>(x, u, W, bias, beta, thr, out);
}